// round 13
// baseline (speedup 1.0000x reference)
#include <cuda_runtime.h>
#include <cuda_fp16.h>
#include <cstdint>

#define B    32768
#define DIN  4096
#define H    100
#define DOUT 1000
#define BN_EPS 1e-4f

#define KC      64
#define NCHUNK  (DIN / KC)         // 64
#define NPAD    128
#define NG      13                 // n8 groups (N=104)

#define PITCH_B   144
#define SPLIT_SZ  (128 * PITCH_B)  // 18432
#define BUF_SZ    (2 * SPLIT_SZ)   // A-hi + B = 36864
#define B_OFF     SPLIT_SZ
#define SB1_OFF   (2 * BUF_SZ)     // 73728
#define XRED_OFF  (SB1_OFF + 512)  // 74240, two 4KB buffers
#define SMEM_TOTAL (XRED_OFF + 8192)

// ---- scratch ----
__device__ float     g_h[(size_t)B * H];
__device__ float     g_scale[H];
__device__ float     g_shift[H];
__device__ unsigned  g_w2p[DOUT * 4];
__device__ __half    g_w1h[(size_t)NPAD * DIN];
__device__ float     g_part[256 * 200];
__device__ float     g_xcs[256 * DIN];
__device__ float     g_xcolsum[DIN];

// ============================================================
// helpers
// ============================================================
__device__ __forceinline__ uint32_t smem_u32(const void* p) {
    uint32_t a;
    asm("{ .reg .u64 t; cvta.to.shared.u64 t, %1; cvt.u32.u64 %0, t; }"
        : "=r"(a) : "l"(p));
    return a;
}
__device__ __forceinline__ void ldsm4(uint32_t* r, uint32_t addr) {
    asm volatile("ldmatrix.sync.aligned.m8n8.x4.shared.b16 {%0,%1,%2,%3}, [%4];"
                 : "=r"(r[0]), "=r"(r[1]), "=r"(r[2]), "=r"(r[3]) : "r"(addr));
}
__device__ __forceinline__ void ldsm2(uint32_t* r, uint32_t addr) {
    asm volatile("ldmatrix.sync.aligned.m8n8.x2.shared.b16 {%0,%1}, [%2];"
                 : "=r"(r[0]), "=r"(r[1]) : "r"(addr));
}
__device__ __forceinline__ void mma16816(float* d, const uint32_t* a,
                                         const uint32_t* b) {
    asm volatile(
        "mma.sync.aligned.m16n8k16.row.col.f32.f16.f16.f32 "
        "{%0,%1,%2,%3}, {%4,%5,%6,%7}, {%8,%9}, {%0,%1,%2,%3};"
        : "+f"(d[0]), "+f"(d[1]), "+f"(d[2]), "+f"(d[3])
        : "r"(a[0]), "r"(a[1]), "r"(a[2]), "r"(a[3]), "r"(b[0]), "r"(b[1]));
}
__device__ __forceinline__ void cp16(uint32_t saddr, const void* g) {
    asm volatile("cp.async.cg.shared.global [%0], [%1], 16;"
                 :: "r"(saddr), "l"(g) : "memory");
}
#define CP_COMMIT() asm volatile("cp.async.commit_group;" ::: "memory")
#define CP_WAIT0()  asm volatile("cp.async.wait_group 0;"  ::: "memory")

__device__ __forceinline__ uint2 hipack(float4 v, float4& lo) {
    __half2 a = __floats2half2_rn(v.x, v.y);
    __half2 b = __floats2half2_rn(v.z, v.w);
    float2 fa = __half22float2(a), fb = __half22float2(b);
    lo.x = v.x - fa.x; lo.y = v.y - fa.y;
    lo.z = v.z - fb.x; lo.w = v.w - fb.y;
    return make_uint2(*(uint32_t*)&a, *(uint32_t*)&b);
}
__device__ __forceinline__ int sx8(uint32_t pk, int q) {
    return (int)(signed char)((pk >> (8 * q)) & 0xffu);
}

// ============================================================
// Kernel P: pack sign(W1)->fp16 (vectorized) and sign(W2)->bitmask
// ============================================================
__global__ void pack_all(const float* __restrict__ W1,
                         const float* __restrict__ W2) {
    int gb = blockIdx.x, tid = threadIdx.x;
    if (gb < 512) {
        int e   = (gb * 256 + tid) * 4;
        int row = e >> 12, col = e & 4095;
        __half2 h0 = __floats2half2_rn(0.f, 0.f), h1 = h0;
        if (row < H) {
            float4 v = *(const float4*)(W1 + (size_t)row * DIN + col);
            h0 = __floats2half2_rn((v.x >= 0.f) ? 1.f : -1.f,
                                   (v.y >= 0.f) ? 1.f : -1.f);
            h1 = __floats2half2_rn((v.z >= 0.f) ? 1.f : -1.f,
                                   (v.w >= 0.f) ? 1.f : -1.f);
        }
        *(uint2*)((char*)g_w1h + (size_t)e * 2) =
            make_uint2(*(uint32_t*)&h0, *(uint32_t*)&h1);
    } else {
        int j = (gb - 512) * 256 + tid;
        if (j >= DOUT) return;
        unsigned w0 = 0, w1 = 0, w2 = 0, w3 = 0;
        const float* r = W2 + (size_t)j * H;
        #pragma unroll 4
        for (int k = 0; k < 32; k++)  if (r[k]      >= 0.f) w0 |= (1u << k);
        #pragma unroll 4
        for (int k = 0; k < 32; k++)  if (r[32 + k] >= 0.f) w1 |= (1u << k);
        #pragma unroll 4
        for (int k = 0; k < 32; k++)  if (r[64 + k] >= 0.f) w2 |= (1u << k);
        #pragma unroll
        for (int k = 0; k < 4;  k++)  if (r[96 + k] >= 0.f) w3 |= (1u << k);
        g_w2p[j * 4 + 0] = w0; g_w2p[j * 4 + 1] = w1;
        g_w2p[j * 4 + 2] = w2; g_w2p[j * 4 + 3] = w3;
    }
}

// ============================================================
// Kernel G: gemm1 hi-only fp16 MMA, 2 CTAs/SM
// ============================================================
__global__ void __launch_bounds__(256, 2)
gemm1_mma(const float* __restrict__ x, const float* __restrict__ b1) {
    extern __shared__ char smem[];
    const uint32_t sm_base = smem_u32(smem);
    const int tid  = threadIdx.x;
    const int warp = tid >> 5;
    const int lane = tid & 31;
    const int row0 = blockIdx.x * 128;

    float* sb1 = (float*)(smem + SB1_OFF);
    if (tid < 104) sb1[tid] = (tid < H) ? b1[tid] : 0.f;

    {
        #pragma unroll
        for (int i = 0; i < 4; i++) {
            int idx = tid + i * 256;
            int r = idx >> 3, q = idx & 7;
            cp16(sm_base + B_OFF + (uint32_t)(r * PITCH_B + q * 16),
                 (const char*)g_w1h + (size_t)r * (DIN * 2) + q * 16);
        }
        CP_COMMIT();
        const float* xp = x + (size_t)row0 * DIN;
        float cs0 = 0.f, cs1 = 0.f, cs2 = 0.f, cs3 = 0.f;
        #pragma unroll
        for (int i = 0; i < 8; i++) {
            int idx = tid + i * 256;
            int r = idx >> 4, q = idx & 15;
            float4 v = __ldg((const float4*)(xp + (size_t)r * DIN + q * 4));
            float4 lo;
            uint2 hi = hipack(v, lo);
            *(uint2*)(smem + r * PITCH_B + q * 8) = hi;
            cs0 += lo.x; cs1 += lo.y; cs2 += lo.z; cs3 += lo.w;
        }
        float* xw = (float*)(smem + XRED_OFF);
        *(float4*)&xw[tid * 4] = make_float4(cs0, cs1, cs2, cs3);
        CP_WAIT0();
    }
    __syncthreads();

    float acc[NG * 4];
    #pragma unroll
    for (int i = 0; i < NG * 4; i++) acc[i] = 0.f;

    const uint32_t a_loff = (uint32_t)((warp * 16 + (lane & 15)) * PITCH_B +
                                       ((lane >> 4) * 8) * 2);
    const uint32_t b_loff = (uint32_t)(((lane >> 4) * 8 + (lane & 7)) * PITCH_B +
                                       (((lane >> 3) & 1) * 8) * 2);

    for (int c = 0; c < NCHUNK; c++) {
        const int buf = c & 1;
        const uint32_t abase = sm_base + buf * BUF_SZ;
        const uint32_t nbase = sm_base + (buf ^ 1) * BUF_SZ;

        if (tid < 64) {
            const float* xr = (const float*)(smem + XRED_OFF + (c & 1) * 4096);
            int q = tid >> 2, j = tid & 3;
            float sum = 0.f;
            #pragma unroll
            for (int m = 0; m < 16; m++) sum += xr[(q + 16 * m) * 4 + j];
            g_xcs[blockIdx.x * DIN + c * 64 + tid] = sum;
        }

        if (c < NCHUNK - 1) {
            const char* wp = (const char*)g_w1h + (size_t)(c + 1) * 128;
            #pragma unroll
            for (int i = 0; i < 4; i++) {
                int idx = tid + i * 256;
                int r = idx >> 3, q = idx & 7;
                cp16(nbase + B_OFF + (uint32_t)(r * PITCH_B + q * 16),
                     wp + (size_t)r * (DIN * 2) + q * 16);
            }
        }
        CP_COMMIT();

        #pragma unroll
        for (int ks = 0; ks < 4; ks++) {
            uint32_t bf[NG * 2];
            #pragma unroll
            for (int gp = 0; gp < 6; gp++)
                ldsm4(bf + 4 * gp, abase + B_OFF + gp * (16 * PITCH_B) +
                      b_loff + ks * 32);
            ldsm2(bf + 24, abase + B_OFF + (96 + (lane & 7)) * PITCH_B +
                  (((lane >> 3) & 1) * 8) * 2 + ks * 32);
            uint32_t a[4];
            ldsm4(a, abase + a_loff + ks * 32);
            #pragma unroll
            for (int g = 0; g < NG; g++)
                mma16816(acc + g * 4, a, bf + 2 * g);
        }

        if (c < NCHUNK - 1) {
            const float* xp = x + (size_t)row0 * DIN + (c + 1) * KC;
            char* base = smem + (buf ^ 1) * BUF_SZ;
            float cs0 = 0.f, cs1 = 0.f, cs2 = 0.f, cs3 = 0.f;
            #pragma unroll
            for (int i = 0; i < 8; i++) {
                int idx = tid + i * 256;
                int r = idx >> 4, q = idx & 15;
                float4 v = __ldg((const float4*)(xp + (size_t)r * DIN + q * 4));
                float4 lo;
                uint2 hi = hipack(v, lo);
                *(uint2*)(base + r * PITCH_B + q * 8) = hi;
                cs0 += lo.x; cs1 += lo.y; cs2 += lo.z; cs3 += lo.w;
            }
            float* xw = (float*)(smem + XRED_OFF + ((c + 1) & 1) * 4096);
            *(float4*)&xw[tid * 4] = make_float4(cs0, cs1, cs2, cs3);
        }
        CP_WAIT0();
        __syncthreads();
    }

    const int gr = row0 + warp * 16 + (lane >> 2);
    const int cb = (lane & 3) * 2;
    #pragma unroll
    for (int g = 0; g < NG; g++) {
        int c0 = g * 8 + cb;
        if (c0 < H) {
            float2 lo, hi;
            lo.x = acc[g*4+0] + sb1[c0];
            lo.y = acc[g*4+1] + sb1[c0 + 1];
            hi.x = acc[g*4+2] + sb1[c0];
            hi.y = acc[g*4+3] + sb1[c0 + 1];
            *(float2*)(g_h + (size_t)gr * H + c0)       = lo;
            *(float2*)(g_h + (size_t)(gr + 8) * H + c0) = hi;
        }
    }

    __syncthreads();
    float s = 0.f, s2 = 0.f;
    if (tid < 200) {
        int f = tid % 100;
        for (int rr = tid / 100; rr < 128; rr += 2) {
            float v = g_h[(size_t)(row0 + rr) * H + f];
            s += v;
            s2 = fmaf(v, v, s2);
        }
    }
    float* red = (float*)smem;
    if (tid < 200) { red[tid] = s; red[256 + tid] = s2; }
    __syncthreads();
    if (tid < 100) {
        g_part[blockIdx.x * 200 + tid]       = red[tid] + red[tid + 100];
        g_part[blockIdx.x * 200 + 100 + tid] = red[256 + tid] + red[356 + tid];
    }
}

// ============================================================
// Kernel R: reduce per-CTA lo colsums -> g_xcolsum
// ============================================================
__global__ void xcs_reduce() {
    __shared__ float sm[256];
    int kk = threadIdx.x & 63, cg = threadIdx.x >> 6;
    int k = blockIdx.x * 64 + kk;
    float s = 0.f;
    for (int c = cg * 64; c < cg * 64 + 64; c++) s += g_xcs[c * DIN + k];
    sm[threadIdx.x] = s;
    __syncthreads();
    if (cg == 0)
        g_xcolsum[k] = sm[kk] + sm[64 + kk] + sm[128 + kk] + sm[192 + kk];
}

// ============================================================
// Kernel S: bn_finish — 256 threads/feature, exact mu
// ============================================================
__global__ void bn_finish(const float* __restrict__ gamma,
                          const float* __restrict__ beta) {
    __shared__ float rs[256], rs2[256], rd[256];
    const int f   = blockIdx.x;
    const int tid = threadIdx.x;

    float s  = g_part[tid * 200 + f];
    float s2 = g_part[tid * 200 + 100 + f];

    float d = 0.f;
    const __half* wr = g_w1h + (size_t)f * DIN;
    #pragma unroll
    for (int t = 0; t < 16; t++) {
        int k = tid + 256 * t;
        d = fmaf(g_xcolsum[k], __half2float(wr[k]), d);
    }
    rs[tid] = s; rs2[tid] = s2; rd[tid] = d;
    __syncthreads();
    #pragma unroll
    for (int off = 128; off > 0; off >>= 1) {
        if (tid < off) {
            rs[tid]  += rs[tid + off];
            rs2[tid] += rs2[tid + off];
            rd[tid]  += rd[tid + off];
        }
        __syncthreads();
    }
    if (tid == 0) {
        float mu_hi = rs[0] * (1.f / B);
        float mu    = mu_hi + rd[0] * (1.f / B);
        float m2    = rs2[0] * (1.f / B);
        float var   = m2 - mu_hi * mu_hi;
        float sc    = gamma[f] * rsqrtf(var + BN_EPS);
        g_scale[f] = sc;
        g_shift[f] = fmaf(-mu, sc, beta[f]);
    }
}

// ============================================================
// Kernel H: head — byte-packed exact logits, fixed-shift softmax,
// fixup fused
// ============================================================
#define LOG2E 1.4426950408889634f
#define LN2   0.69314718055994531f
#define MXF   40.0f   // fixed shift: terms <= 2^86.6, sum >= 2^-72 (safe)

__global__ __launch_bounds__(256, 4)
void head(const float* __restrict__ x, const float* __restrict__ b1,
          const float* __restrict__ b2, float* __restrict__ out) {
    __shared__ uint4 sw4[DOUT];
    __shared__ float sb[DOUT];
    __shared__ float ssc[H], ssh[H], sb1s[H];

    const int tid = threadIdx.x;
    for (int i = tid; i < DOUT; i += 256) {
        sw4[i] = ((const uint4*)g_w2p)[i];
        sb[i]  = b2[i];
    }
    if (tid < H) { ssc[tid] = g_scale[tid]; ssh[tid] = g_shift[tid];
                   sb1s[tid] = b1[tid]; }
    __syncthreads();

    const int lane = tid & 31;
    const int warp = tid >> 5;
    const int row  = blockIdx.x * 8 + warp;

    const float* hr = g_h + (size_t)row * H;
    const float* xr = x + (size_t)row * DIN;

    float hn0 = fmaf(hr[lane],      ssc[lane],      ssh[lane]);
    float hn1 = fmaf(hr[32 + lane], ssc[32 + lane], ssh[32 + lane]);
    float hn2 = fmaf(hr[64 + lane], ssc[64 + lane], ssh[64 + lane]);
    float hn3 = (lane < 4) ?
                fmaf(hr[96 + lane], ssc[96 + lane], ssh[96 + lane]) : -1.f;

    // ---- inline exact fixup of boundary entries ----
    #pragma unroll
    for (int grp = 0; grp < 4; grp++) {
        float hn = (grp == 0) ? hn0 : (grp == 1) ? hn1 : (grp == 2) ? hn2 : hn3;
        bool flag = (grp < 3 || lane < 4) &&
                    (fabsf(hn) < 0.12f * fabsf(ssc[(grp * 32 + lane) % H]));
        unsigned m = __ballot_sync(0xffffffffu, flag);
        while (m) {
            int bpos = __ffs(m) - 1;
            m &= m - 1;
            int feat = grp * 32 + bpos;
            const __half* wr = g_w1h + (size_t)feat * DIN;
            float s = 0.f, comp = 0.f;
            #pragma unroll 4
            for (int t = 0; t < 128; t++) {
                int k = lane + 32 * t;
                float term = xr[k] * __half2float(wr[k]);
                float y  = __fsub_rn(term, comp);
                float t2 = __fadd_rn(s, y);
                comp = __fsub_rn(__fsub_rn(t2, s), y);
                s = t2;
            }
            s = __fadd_rn(s, comp);
            #pragma unroll
            for (int off = 16; off > 0; off >>= 1)
                s += __shfl_xor_sync(0xffffffffu, s, off);
            if (lane == bpos) {
                float fix = fmaf(s + sb1s[feat], ssc[feat], ssh[feat]);
                if (grp == 0) hn0 = fix;
                else if (grp == 1) hn1 = fix;
                else if (grp == 2) hn2 = fix;
                else hn3 = fix;
            }
        }
    }

    unsigned a0 = __ballot_sync(0xffffffffu, hn0 >= 0.f);
    unsigned a1 = __ballot_sync(0xffffffffu, hn1 >= 0.f);
    unsigned a2 = __ballot_sync(0xffffffffu, hn2 >= 0.f);
    unsigned a3 = __ballot_sync(0xffffffffu, (lane < 4) && (hn3 >= 0.f));

    // ---- single pass: popc -> packed int8 logits + exp-sum (fixed shift) ----
    uint32_t pk[8];
    float s = 0.f;
    #pragma unroll
    for (int i = 0; i < 8; i++) {
        int jb = i * 128 + lane * 4;
        uint32_t p = 0;
        if (jb < DOUT) {
            float4 bias = *(const float4*)&sb[jb];
            #pragma unroll
            for (int q = 0; q < 4; q++) {
                uint4 w = sw4[jb + q];
                int pc = __popc(a0 ^ w.x) + __popc(a1 ^ w.y) +
                         __popc(a2 ^ w.z) + __popc(a3 ^ w.w);
                int v = H - 2 * pc;
                p |= (uint32_t)(v & 255) << (8 * q);
                float bi = (q == 0) ? bias.x : (q == 1) ? bias.y :
                           (q == 2) ? bias.z : bias.w;
                s += exp2f(((float)v + bi - MXF) * LOG2E);
            }
        }
        pk[i] = p;
    }
    #pragma unroll
    for (int off = 16; off > 0; off >>= 1)
        s += __shfl_xor_sync(0xffffffffu, s, off);
    float lse = fmaf(LN2, __log2f(s), MXF);

    // ---- store ----
    float* orow = out + (size_t)row * DOUT;
    #pragma unroll
    for (int i = 0; i < 8; i++) {
        int jb = i * 128 + lane * 4;
        if (jb < DOUT) {
            float4 bias = *(const float4*)&sb[jb];
            float4 v;
            v.x = (float)sx8(pk[i], 0) + bias.x - lse;
            v.y = (float)sx8(pk[i], 1) + bias.y - lse;
            v.z = (float)sx8(pk[i], 2) + bias.z - lse;
            v.w = (float)sx8(pk[i], 3) + bias.w - lse;
            *(float4*)(orow + jb) = v;
        }
    }
}

// ============================================================
// Launch
// ============================================================
extern "C" void kernel_launch(void* const* d_in, const int* in_sizes, int n_in,
                              void* d_out, int out_size) {
    (void)in_sizes; (void)n_in; (void)out_size;
    const float* x     = (const float*)d_in[0];
    const float* W1    = (const float*)d_in[1];
    const float* b1    = (const float*)d_in[2];
    const float* gamma = (const float*)d_in[3];
    const float* beta  = (const float*)d_in[4];
    const float* W2    = (const float*)d_in[5];
    const float* b2    = (const float*)d_in[6];
    float* out = (float*)d_out;

    static int smem_set = 0;
    if (!smem_set) {
        cudaFuncSetAttribute(gemm1_mma, cudaFuncAttributeMaxDynamicSharedMemorySize,
                             SMEM_TOTAL);
        smem_set = 1;
    }

    pack_all<<<516, 256>>>(W1, W2);
    gemm1_mma<<<B / 128, 256, SMEM_TOTAL>>>(x, b1);
    xcs_reduce<<<DIN / 64, 256>>>();
    bn_finish<<<H, 256>>>(gamma, beta);
    head<<<B / 8, 256>>>(x, b1, b2, out);
}